// round 11
// baseline (speedup 1.0000x reference)
#include <cuda_runtime.h>
#include <cuda_bf16.h>
#include <cstdint>

#define HIDDEN   128
#define NGRAPH   512
#define NCLS     10
#define LAYERS   3
#define MAXN     100000
#define NH       (12800000)   /* MAXN * HIDDEN */

// ---------------- scratch (device globals: no allocation allowed) ----------
__device__ float g_agg[NH];
__device__ float g_tmp[NH];
__device__ float g_z2 [NH];
__device__ float g_hA [NH];
__device__ float g_hB [NH];
__device__ float g_pool[NGRAPH * LAYERS * HIDDEN];   // [512,384]
__device__ float g_cnt [NGRAPH];
__device__ float g_stats[2 * HIDDEN];                // colsum, colsumsq

// ---------------- helpers ---------------------------------------------------
__device__ __forceinline__ void red_add_v4(float* addr, float a, float b, float c, float d) {
    asm volatile("red.global.add.v4.f32 [%0], {%1, %2, %3, %4};"
                 :: "l"(addr), "f"(a), "f"(b), "f"(c), "f"(d) : "memory");
}

// ---------------- per-graph node counts -------------------------------------
__global__ void count_kernel(const int* __restrict__ batch, float* __restrict__ cnt, int N) {
    int i = blockIdx.x * blockDim.x + threadIdx.x;
    if (i < N) atomicAdd(&cnt[batch[i]], 1.0f);
}

// ---------------- edge scatter: agg[dst] += h[src] --------------------------
// one warp per edge, each lane handles 4 contiguous channels (float4)
__global__ void scatter_kernel(const float* __restrict__ h, const int* __restrict__ ei,
                               float* __restrict__ agg, int E) {
    long long t = (long long)blockIdx.x * blockDim.x + threadIdx.x;
    int e = (int)(t >> 5);
    if (e >= E) return;
    int lane = (int)(t & 31);
    int src = ei[e];
    int dst = ei[E + e];
    float4 v = ((const float4*)h)[(size_t)src * 32 + lane];
    float* p = agg + (size_t)dst * HIDDEN + lane * 4;
    red_add_v4(p, v.x, v.y, v.z, v.w);
}

// ---------------- SGEMM: C = relu( Aeff @ W + bias ) ------------------------
// Aeff = (A2 ? alpha*A + A2 : A),  alpha = 1 + eps_gin[l]
// [N,128] @ [128,128], BM=128, BN=128, BK=32, 256 threads, 8x8 reg tile.
__global__ __launch_bounds__(256)
void gemm_relu_kernel(const float* __restrict__ A, const float* __restrict__ A2,
                      const float* __restrict__ epsp,
                      const float* __restrict__ W, const float* __restrict__ bias,
                      float* __restrict__ C, int N) {
    __shared__ __align__(16) float As[32][HIDDEN + 4];  // transposed: As[k][m]
    __shared__ __align__(16) float Bs[32][HIDDEN];      // Bs[k][n]

    const int tid = threadIdx.x;
    const int tx = tid & 15;           // 0..15 -> col groups
    const int ty = tid >> 4;           // 0..15 -> row groups
    const int row0 = ty * 8;
    const int col0 = tx * 8;
    const int block_m = blockIdx.x * 128;

    float alpha = 1.0f;
    if (A2) alpha = 1.0f + __ldg(epsp);

    float acc[8][8];
#pragma unroll
    for (int i = 0; i < 8; i++)
#pragma unroll
        for (int j = 0; j < 8; j++) acc[i][j] = 0.0f;

    for (int kk = 0; kk < HIDDEN; kk += 32) {
        // ---- load A tile (128 x 32) into As transposed -----------------
#pragma unroll
        for (int it = 0; it < 4; it++) {
            int flat = tid + it * 256;           // 0..1023 (each = one float4)
            int m    = flat >> 3;                // 0..127
            int k4   = (flat & 7) * 4;           // 0,4,...,28
            int gm   = block_m + m;
            float4 v = make_float4(0.f, 0.f, 0.f, 0.f);
            if (gm < N) {
                v = *(const float4*)(A + (size_t)gm * HIDDEN + kk + k4);
                if (A2) {
                    float4 u = *(const float4*)(A2 + (size_t)gm * HIDDEN + kk + k4);
                    v.x = fmaf(alpha, v.x, u.x);
                    v.y = fmaf(alpha, v.y, u.y);
                    v.z = fmaf(alpha, v.z, u.z);
                    v.w = fmaf(alpha, v.w, u.w);
                }
            }
            As[k4 + 0][m] = v.x;
            As[k4 + 1][m] = v.y;
            As[k4 + 2][m] = v.z;
            As[k4 + 3][m] = v.w;
        }
        // ---- load W tile (32 x 128) into Bs -----------------------------
#pragma unroll
        for (int it = 0; it < 4; it++) {
            int flat = tid + it * 256;           // each = one float4
            int k    = flat >> 5;                // 0..31
            int n4   = (flat & 31) * 4;          // 0..124
            float4 v = *(const float4*)(W + (size_t)(kk + k) * HIDDEN + n4);
            *(float4*)&Bs[k][n4] = v;
        }
        __syncthreads();

#pragma unroll 8
        for (int k = 0; k < 32; k++) {
            float4 a0 = *(const float4*)&As[k][row0];
            float4 a1 = *(const float4*)&As[k][row0 + 4];
            float4 b0 = *(const float4*)&Bs[k][col0];
            float4 b1 = *(const float4*)&Bs[k][col0 + 4];
            float a[8] = {a0.x, a0.y, a0.z, a0.w, a1.x, a1.y, a1.z, a1.w};
            float b[8] = {b0.x, b0.y, b0.z, b0.w, b1.x, b1.y, b1.z, b1.w};
#pragma unroll
            for (int i = 0; i < 8; i++)
#pragma unroll
                for (int j = 0; j < 8; j++)
                    acc[i][j] = fmaf(a[i], b[j], acc[i][j]);
        }
        __syncthreads();
    }

    // ---- epilogue: bias + relu ---------------------------------------------
    float bv[8];
#pragma unroll
    for (int j = 0; j < 8; j++) bv[j] = bias[col0 + j];

#pragma unroll
    for (int i = 0; i < 8; i++) {
        int gm = block_m + row0 + i;
        if (gm < N) {
            float4 o0, o1;
            o0.x = fmaxf(acc[i][0] + bv[0], 0.f);
            o0.y = fmaxf(acc[i][1] + bv[1], 0.f);
            o0.z = fmaxf(acc[i][2] + bv[2], 0.f);
            o0.w = fmaxf(acc[i][3] + bv[3], 0.f);
            o1.x = fmaxf(acc[i][4] + bv[4], 0.f);
            o1.y = fmaxf(acc[i][5] + bv[5], 0.f);
            o1.z = fmaxf(acc[i][6] + bv[6], 0.f);
            o1.w = fmaxf(acc[i][7] + bv[7], 0.f);
            *(float4*)(C + (size_t)gm * HIDDEN + col0)     = o0;
            *(float4*)(C + (size_t)gm * HIDDEN + col0 + 4) = o1;
        }
    }
}

// ---------------- BN column stats (sum, sumsq) ------------------------------
__global__ void stats_kernel(const float* __restrict__ z, float* __restrict__ stats, int N) {
    int c = threadIdx.x;  // 0..127
    float s = 0.f, s2 = 0.f;
    for (int r = blockIdx.x; r < N; r += gridDim.x) {
        float v = z[(size_t)r * HIDDEN + c];
        s  += v;
        s2 += v * v;
    }
    atomicAdd(&stats[c], s);
    atomicAdd(&stats[HIDDEN + c], s2);
}

// ---------------- BN normalize + fused mean-pool accumulate -----------------
__global__ void bn_pool_kernel(const float* __restrict__ z, const float* __restrict__ stats,
                               const float* __restrict__ gamma, const float* __restrict__ beta,
                               const int* __restrict__ batch,
                               float* __restrict__ hout, float* __restrict__ pool,
                               int N, int loff) {
    int t = blockIdx.x * blockDim.x + threadIdx.x;
    int row = t >> 5;
    if (row >= N) return;
    int lane = t & 31;
    int c = lane * 4;
    const float invN = 1.0f / (float)N;

    float4 v = ((const float4*)z)[(size_t)row * 32 + lane];
    float vv[4] = {v.x, v.y, v.z, v.w};
    float o[4];
#pragma unroll
    for (int j = 0; j < 4; j++) {
        float mean = stats[c + j] * invN;
        float var  = stats[HIDDEN + c + j] * invN - mean * mean;
        float sc   = gamma[c + j] * rsqrtf(var + 1e-5f);
        o[j] = (vv[j] - mean) * sc + beta[c + j];
    }
    ((float4*)hout)[(size_t)row * 32 + lane] = make_float4(o[0], o[1], o[2], o[3]);

    int b = batch[row];
    float* p = pool + (size_t)b * (LAYERS * HIDDEN) + loff + c;
    red_add_v4(p, o[0], o[1], o[2], o[3]);
}

// ---------------- readout head: mean-pool -> relu(fc1) -> fc2 ---------------
__global__ void head_kernel(const float* __restrict__ pool, const float* __restrict__ cnt,
                            const float* __restrict__ l1w, const float* __restrict__ l1b,
                            const float* __restrict__ l2w, const float* __restrict__ l2b,
                            float* __restrict__ out) {
    __shared__ float grow[LAYERS * HIDDEN];
    __shared__ float o1[HIDDEN];
    int g = blockIdx.x, t = threadIdx.x;
    float inv = 1.0f / fmaxf(cnt[g], 1.0f);
    for (int j = t; j < LAYERS * HIDDEN; j += HIDDEN)
        grow[j] = pool[(size_t)g * (LAYERS * HIDDEN) + j] * inv;
    __syncthreads();

    float acc = l1b[t];
    for (int j = 0; j < LAYERS * HIDDEN; j++)
        acc = fmaf(grow[j], l1w[(size_t)j * HIDDEN + t], acc);
    o1[t] = fmaxf(acc, 0.f);
    __syncthreads();

    if (t < NCLS) {
        float a = l2b[t];
        for (int c2 = 0; c2 < HIDDEN; c2++)
            a = fmaf(o1[c2], l2w[(size_t)c2 * NCLS + t], a);
        out[(size_t)g * NCLS + t] = a;
    }
}

// ---------------- launcher ---------------------------------------------------
extern "C" void kernel_launch(void* const* d_in, const int* in_sizes, int n_in,
                              void* d_out, int out_size) {
    const float* x     = (const float*)d_in[0];
    const int*   ei    = (const int*)  d_in[1];
    const int*   batch = (const int*)  d_in[2];
    const float* W1    = (const float*)d_in[3];
    const float* b1    = (const float*)d_in[4];
    const float* W2    = (const float*)d_in[5];
    const float* b2    = (const float*)d_in[6];
    const float* gamma = (const float*)d_in[7];
    const float* beta  = (const float*)d_in[8];
    const float* epsg  = (const float*)d_in[9];
    const float* l1w   = (const float*)d_in[10];
    const float* l1b   = (const float*)d_in[11];
    const float* l2w   = (const float*)d_in[12];
    const float* l2b   = (const float*)d_in[13];
    float* out = (float*)d_out;

    const int N = in_sizes[0] / HIDDEN;
    const int E = in_sizes[1] / 2;

    float *agg, *tmp, *z2, *hA, *hB, *pool, *cnt, *stats;
    cudaGetSymbolAddress((void**)&agg,   g_agg);
    cudaGetSymbolAddress((void**)&tmp,   g_tmp);
    cudaGetSymbolAddress((void**)&z2,    g_z2);
    cudaGetSymbolAddress((void**)&hA,    g_hA);
    cudaGetSymbolAddress((void**)&hB,    g_hB);
    cudaGetSymbolAddress((void**)&pool,  g_pool);
    cudaGetSymbolAddress((void**)&cnt,   g_cnt);
    cudaGetSymbolAddress((void**)&stats, g_stats);

    cudaMemsetAsync(pool, 0, (size_t)NGRAPH * LAYERS * HIDDEN * sizeof(float), 0);
    cudaMemsetAsync(cnt,  0, (size_t)NGRAPH * sizeof(float), 0);
    count_kernel<<<(N + 255) / 256, 256>>>(batch, cnt, N);

    const int gemm_grid    = (N + 127) / 128;
    const long long sc_thr = (long long)E * 32;
    const int sc_grid      = (int)((sc_thr + 255) / 256);
    const int bn_grid      = (N * 32 + 255) / 256;

    const float* hin = x;
    float* houts[LAYERS] = {hA, hB, hA};

    for (int l = 0; l < LAYERS; l++) {
        cudaMemsetAsync(agg, 0, (size_t)N * HIDDEN * sizeof(float), 0);
        scatter_kernel<<<sc_grid, 256>>>(hin, ei, agg, E);

        gemm_relu_kernel<<<gemm_grid, 256>>>(hin, agg, epsg + l,
                                             W1 + (size_t)l * HIDDEN * HIDDEN,
                                             b1 + (size_t)l * HIDDEN, tmp, N);
        gemm_relu_kernel<<<gemm_grid, 256>>>(tmp, nullptr, nullptr,
                                             W2 + (size_t)l * HIDDEN * HIDDEN,
                                             b2 + (size_t)l * HIDDEN, z2, N);

        cudaMemsetAsync(stats, 0, 2 * HIDDEN * sizeof(float), 0);
        stats_kernel<<<512, HIDDEN>>>(z2, stats, N);

        bn_pool_kernel<<<bn_grid, 256>>>(z2, stats,
                                         gamma + (size_t)l * HIDDEN,
                                         beta  + (size_t)l * HIDDEN,
                                         batch, houts[l], pool, N, l * HIDDEN);
        hin = houts[l];
    }

    head_kernel<<<NGRAPH, HIDDEN>>>(pool, cnt, l1w, l1b, l2w, l2b, out);
}

// round 12
// speedup vs baseline: 1.3217x; 1.3217x over previous
#include <cuda_runtime.h>
#include <cuda_bf16.h>
#include <cstdint>

#define HIDDEN   128
#define NGRAPH   512
#define NCLS     10
#define LAYERS   3
#define MAXN     100000
#define MAXE     1600000
#define NH       (12800000)   /* MAXN * HIDDEN */

// ---------------- scratch (device globals: no allocation allowed) ----------
__device__ float g_agg[NH];
__device__ float g_tmp[NH];
__device__ float g_z2 [NH];
__device__ float g_hA [NH];
__device__ float g_hB [NH];
__device__ float g_pool[NGRAPH * LAYERS * HIDDEN];
__device__ float g_cnt [NGRAPH];
__device__ float g_stats[2 * HIDDEN];
// CSR scratch
__device__ int g_deg   [MAXN + 1];
__device__ int g_rowptr[MAXN + 1];
__device__ int g_cursor[MAXN];
__device__ int g_csr   [MAXE];
__device__ int g_bsum  [256];

// ---------------- helpers ---------------------------------------------------
__device__ __forceinline__ void red_add_v4(float* addr, float a, float b, float c, float d) {
    asm volatile("red.global.add.v4.f32 [%0], {%1, %2, %3, %4};"
                 :: "l"(addr), "f"(a), "f"(b), "f"(c), "f"(d) : "memory");
}

// ---------------- per-graph node counts -------------------------------------
__global__ void count_kernel(const int* __restrict__ batch, float* __restrict__ cnt, int N) {
    int i = blockIdx.x * blockDim.x + threadIdx.x;
    if (i < N) atomicAdd(&cnt[batch[i]], 1.0f);
}

// ---------------- CSR build --------------------------------------------------
__global__ void deg_kernel(const int* __restrict__ ei, int* __restrict__ deg, int E) {
    int e = blockIdx.x * blockDim.x + threadIdx.x;
    if (e < E) atomicAdd(&deg[ei[E + e]], 1);   // dst
}

// block-level exclusive scan (1024 threads/block)
__global__ void scan1_kernel(const int* __restrict__ in, int* __restrict__ out,
                             int* __restrict__ bsum, int M) {
    int gid = blockIdx.x * 1024 + threadIdx.x;
    int v = (gid < M) ? in[gid] : 0;
    int lane = threadIdx.x & 31, wid = threadIdx.x >> 5;
    int x = v;
#pragma unroll
    for (int o = 1; o < 32; o <<= 1) {
        int y = __shfl_up_sync(0xffffffffu, x, o);
        if (lane >= o) x += y;
    }
    __shared__ int ws[32];
    if (lane == 31) ws[wid] = x;
    __syncthreads();
    if (wid == 0) {
        int y = ws[lane];
#pragma unroll
        for (int o = 1; o < 32; o <<= 1) {
            int z = __shfl_up_sync(0xffffffffu, y, o);
            if (lane >= o) y += z;
        }
        ws[lane] = y;
    }
    __syncthreads();
    int excl = x - v + (wid > 0 ? ws[wid - 1] : 0);
    if (gid < M) out[gid] = excl;
    if (threadIdx.x == 0) bsum[blockIdx.x] = ws[31];
}

__global__ void scan2_kernel(int* __restrict__ bsum, int nb) {
    if (threadIdx.x == 0 && blockIdx.x == 0) {
        int run = 0;
        for (int i = 0; i < nb; i++) { int t = bsum[i]; bsum[i] = run; run += t; }
    }
}

__global__ void scan3_kernel(int* __restrict__ out, const int* __restrict__ bsum, int M) {
    int gid = blockIdx.x * 1024 + threadIdx.x;
    if (gid < M) out[gid] += bsum[blockIdx.x];
}

__global__ void fill_kernel(const int* __restrict__ ei, int* __restrict__ cursor,
                            int* __restrict__ csr, int E) {
    int e = blockIdx.x * blockDim.x + threadIdx.x;
    if (e < E) {
        int d = ei[E + e];
        int slot = atomicAdd(&cursor[d], 1);
        csr[slot] = ei[e];   // src
    }
}

// ---------------- CSR gather-aggregate: agg[i] = sum_{j in N(i)} h[j] -------
__global__ void agg_csr_kernel(const float* __restrict__ h, const int* __restrict__ rowptr,
                               const int* __restrict__ csr, float* __restrict__ agg, int N) {
    int t = blockIdx.x * blockDim.x + threadIdx.x;
    int node = t >> 5;
    if (node >= N) return;
    int lane = t & 31;
    int s = rowptr[node], e = rowptr[node + 1];
    float4 a0 = make_float4(0.f, 0.f, 0.f, 0.f);
    float4 a1 = make_float4(0.f, 0.f, 0.f, 0.f);
    int i = s;
    for (; i + 2 <= e; i += 2) {
        int s0 = __ldg(&csr[i]);
        int s1 = __ldg(&csr[i + 1]);
        float4 v0 = ((const float4*)h)[(size_t)s0 * 32 + lane];
        float4 v1 = ((const float4*)h)[(size_t)s1 * 32 + lane];
        a0.x += v0.x; a0.y += v0.y; a0.z += v0.z; a0.w += v0.w;
        a1.x += v1.x; a1.y += v1.y; a1.z += v1.z; a1.w += v1.w;
    }
    if (i < e) {
        int s0 = __ldg(&csr[i]);
        float4 v0 = ((const float4*)h)[(size_t)s0 * 32 + lane];
        a0.x += v0.x; a0.y += v0.y; a0.z += v0.z; a0.w += v0.w;
    }
    a0.x += a1.x; a0.y += a1.y; a0.z += a1.z; a0.w += a1.w;
    ((float4*)agg)[(size_t)node * 32 + lane] = a0;
}

// ---------------- SGEMM: C = relu( Aeff @ W + bias ), packed f32x2 ----------
// Aeff = (A2 ? alpha*A + A2 : A),  alpha = 1 + eps_gin[l]
__global__ __launch_bounds__(256, 2)
void gemm_relu_kernel(const float* __restrict__ A, const float* __restrict__ A2,
                      const float* __restrict__ epsp,
                      const float* __restrict__ W, const float* __restrict__ bias,
                      float* __restrict__ C, int N) {
    __shared__ __align__(16) float As[32][HIDDEN + 8];  // stride 136 floats = 544B (16B mult)
    __shared__ __align__(16) float Bs[32][HIDDEN];

    const int tid = threadIdx.x;
    const int tx = tid & 15;
    const int ty = tid >> 4;
    const int row0 = ty * 8;
    const int col0 = tx * 8;
    const int block_m = blockIdx.x * 128;

    float alpha = 1.0f;
    if (A2) alpha = 1.0f + __ldg(epsp);

    // acc[i2][j]: packed pair of rows (row0+2*i2, row0+2*i2+1), col col0+j
    unsigned long long acc[4][8];
#pragma unroll
    for (int i = 0; i < 4; i++)
#pragma unroll
        for (int j = 0; j < 8; j++) acc[i][j] = 0ull;

    for (int kk = 0; kk < HIDDEN; kk += 32) {
#pragma unroll
        for (int it = 0; it < 4; it++) {
            int flat = tid + it * 256;
            int m    = flat >> 3;
            int k4   = (flat & 7) * 4;
            int gm   = block_m + m;
            float4 v = make_float4(0.f, 0.f, 0.f, 0.f);
            if (gm < N) {
                v = *(const float4*)(A + (size_t)gm * HIDDEN + kk + k4);
                if (A2) {
                    float4 u = *(const float4*)(A2 + (size_t)gm * HIDDEN + kk + k4);
                    v.x = fmaf(alpha, v.x, u.x);
                    v.y = fmaf(alpha, v.y, u.y);
                    v.z = fmaf(alpha, v.z, u.z);
                    v.w = fmaf(alpha, v.w, u.w);
                }
            }
            As[k4 + 0][m] = v.x;
            As[k4 + 1][m] = v.y;
            As[k4 + 2][m] = v.z;
            As[k4 + 3][m] = v.w;
        }
#pragma unroll
        for (int it = 0; it < 4; it++) {
            int flat = tid + it * 256;
            int k    = flat >> 5;
            int n4   = (flat & 31) * 4;
            *(float4*)&Bs[k][n4] = *(const float4*)(W + (size_t)(kk + k) * HIDDEN + n4);
        }
        __syncthreads();

#pragma unroll 8
        for (int k = 0; k < 32; k++) {
            // a: 8 consecutive row values -> 4 natural f32x2 pairs
            ulonglong2 A0 = *(const ulonglong2*)&As[k][row0];
            ulonglong2 A1 = *(const ulonglong2*)&As[k][row0 + 4];
            unsigned long long ap[4] = {A0.x, A0.y, A1.x, A1.y};
            float4 b0 = *(const float4*)&Bs[k][col0];
            float4 b1 = *(const float4*)&Bs[k][col0 + 4];
            float bb[8] = {b0.x, b0.y, b0.z, b0.w, b1.x, b1.y, b1.z, b1.w};
            unsigned long long bd[8];
#pragma unroll
            for (int j = 0; j < 8; j++)
                asm("mov.b64 %0, {%1, %1};" : "=l"(bd[j]) : "f"(bb[j]));
#pragma unroll
            for (int i2 = 0; i2 < 4; i2++)
#pragma unroll
                for (int j = 0; j < 8; j++)
                    asm("fma.rn.f32x2 %0, %1, %2, %0;"
                        : "+l"(acc[i2][j]) : "l"(ap[i2]), "l"(bd[j]));
        }
        __syncthreads();
    }

    // unpack
    float accf[8][8];
#pragma unroll
    for (int i2 = 0; i2 < 4; i2++)
#pragma unroll
        for (int j = 0; j < 8; j++)
            asm("mov.b64 {%0, %1}, %2;"
                : "=f"(accf[2 * i2][j]), "=f"(accf[2 * i2 + 1][j]) : "l"(acc[i2][j]));

    float bv[8];
#pragma unroll
    for (int j = 0; j < 8; j++) bv[j] = bias[col0 + j];

#pragma unroll
    for (int i = 0; i < 8; i++) {
        int gm = block_m + row0 + i;
        if (gm < N) {
            float4 o0, o1;
            o0.x = fmaxf(accf[i][0] + bv[0], 0.f);
            o0.y = fmaxf(accf[i][1] + bv[1], 0.f);
            o0.z = fmaxf(accf[i][2] + bv[2], 0.f);
            o0.w = fmaxf(accf[i][3] + bv[3], 0.f);
            o1.x = fmaxf(accf[i][4] + bv[4], 0.f);
            o1.y = fmaxf(accf[i][5] + bv[5], 0.f);
            o1.z = fmaxf(accf[i][6] + bv[6], 0.f);
            o1.w = fmaxf(accf[i][7] + bv[7], 0.f);
            *(float4*)(C + (size_t)gm * HIDDEN + col0)     = o0;
            *(float4*)(C + (size_t)gm * HIDDEN + col0 + 4) = o1;
        }
    }
}

// ---------------- BN column stats (sum, sumsq) ------------------------------
__global__ void stats_kernel(const float* __restrict__ z, float* __restrict__ stats, int N) {
    int c = threadIdx.x;
    float s = 0.f, s2 = 0.f;
    for (int r = blockIdx.x; r < N; r += gridDim.x) {
        float v = z[(size_t)r * HIDDEN + c];
        s  += v;
        s2 += v * v;
    }
    atomicAdd(&stats[c], s);
    atomicAdd(&stats[HIDDEN + c], s2);
}

// ---------------- BN normalize + fused mean-pool accumulate -----------------
__global__ void bn_pool_kernel(const float* __restrict__ z, const float* __restrict__ stats,
                               const float* __restrict__ gamma, const float* __restrict__ beta,
                               const int* __restrict__ batch,
                               float* __restrict__ hout, float* __restrict__ pool,
                               int N, int loff) {
    int t = blockIdx.x * blockDim.x + threadIdx.x;
    int row = t >> 5;
    if (row >= N) return;
    int lane = t & 31;
    int c = lane * 4;
    const float invN = 1.0f / (float)N;

    float4 v = ((const float4*)z)[(size_t)row * 32 + lane];
    float vv[4] = {v.x, v.y, v.z, v.w};
    float o[4];
#pragma unroll
    for (int j = 0; j < 4; j++) {
        float mean = stats[c + j] * invN;
        float var  = stats[HIDDEN + c + j] * invN - mean * mean;
        float sc   = gamma[c + j] * rsqrtf(var + 1e-5f);
        o[j] = (vv[j] - mean) * sc + beta[c + j];
    }
    ((float4*)hout)[(size_t)row * 32 + lane] = make_float4(o[0], o[1], o[2], o[3]);

    int b = batch[row];
    float* p = pool + (size_t)b * (LAYERS * HIDDEN) + loff + c;
    red_add_v4(p, o[0], o[1], o[2], o[3]);
}

// ---------------- readout head ----------------------------------------------
__global__ void head_kernel(const float* __restrict__ pool, const float* __restrict__ cnt,
                            const float* __restrict__ l1w, const float* __restrict__ l1b,
                            const float* __restrict__ l2w, const float* __restrict__ l2b,
                            float* __restrict__ out) {
    __shared__ float grow[LAYERS * HIDDEN];
    __shared__ float o1[HIDDEN];
    int g = blockIdx.x, t = threadIdx.x;
    float inv = 1.0f / fmaxf(cnt[g], 1.0f);
    for (int j = t; j < LAYERS * HIDDEN; j += HIDDEN)
        grow[j] = pool[(size_t)g * (LAYERS * HIDDEN) + j] * inv;
    __syncthreads();

    float acc = l1b[t];
    for (int j = 0; j < LAYERS * HIDDEN; j++)
        acc = fmaf(grow[j], l1w[(size_t)j * HIDDEN + t], acc);
    o1[t] = fmaxf(acc, 0.f);
    __syncthreads();

    if (t < NCLS) {
        float a = l2b[t];
        for (int c2 = 0; c2 < HIDDEN; c2++)
            a = fmaf(o1[c2], l2w[(size_t)c2 * NCLS + t], a);
        out[(size_t)g * NCLS + t] = a;
    }
}

// ---------------- launcher ---------------------------------------------------
extern "C" void kernel_launch(void* const* d_in, const int* in_sizes, int n_in,
                              void* d_out, int out_size) {
    const float* x     = (const float*)d_in[0];
    const int*   ei    = (const int*)  d_in[1];
    const int*   batch = (const int*)  d_in[2];
    const float* W1    = (const float*)d_in[3];
    const float* b1    = (const float*)d_in[4];
    const float* W2    = (const float*)d_in[5];
    const float* b2    = (const float*)d_in[6];
    const float* gamma = (const float*)d_in[7];
    const float* beta  = (const float*)d_in[8];
    const float* epsg  = (const float*)d_in[9];
    const float* l1w   = (const float*)d_in[10];
    const float* l1b   = (const float*)d_in[11];
    const float* l2w   = (const float*)d_in[12];
    const float* l2b   = (const float*)d_in[13];
    float* out = (float*)d_out;

    const int N = in_sizes[0] / HIDDEN;
    const int E = in_sizes[1] / 2;
    const int M = N + 1;

    float *agg, *tmp, *z2, *hA, *hB, *pool, *cnt, *stats;
    int *deg, *rowptr, *cursor, *csr, *bsum;
    cudaGetSymbolAddress((void**)&agg,    g_agg);
    cudaGetSymbolAddress((void**)&tmp,    g_tmp);
    cudaGetSymbolAddress((void**)&z2,     g_z2);
    cudaGetSymbolAddress((void**)&hA,     g_hA);
    cudaGetSymbolAddress((void**)&hB,     g_hB);
    cudaGetSymbolAddress((void**)&pool,   g_pool);
    cudaGetSymbolAddress((void**)&cnt,    g_cnt);
    cudaGetSymbolAddress((void**)&stats,  g_stats);
    cudaGetSymbolAddress((void**)&deg,    g_deg);
    cudaGetSymbolAddress((void**)&rowptr, g_rowptr);
    cudaGetSymbolAddress((void**)&cursor, g_cursor);
    cudaGetSymbolAddress((void**)&csr,    g_csr);
    cudaGetSymbolAddress((void**)&bsum,   g_bsum);

    // ---- per-graph counts + pool init ----
    cudaMemsetAsync(pool, 0, (size_t)NGRAPH * LAYERS * HIDDEN * sizeof(float), 0);
    cudaMemsetAsync(cnt,  0, (size_t)NGRAPH * sizeof(float), 0);
    count_kernel<<<(N + 255) / 256, 256>>>(batch, cnt, N);

    // ---- CSR build (once; reused for all 3 layers) ----
    const int nb = (M + 1023) / 1024;
    cudaMemsetAsync(deg, 0, (size_t)M * sizeof(int), 0);
    deg_kernel<<<(E + 255) / 256, 256>>>(ei, deg, E);
    scan1_kernel<<<nb, 1024>>>(deg, rowptr, bsum, M);
    scan2_kernel<<<1, 32>>>(bsum, nb);
    scan3_kernel<<<nb, 1024>>>(rowptr, bsum, M);
    cudaMemcpyAsync(cursor, rowptr, (size_t)N * sizeof(int), cudaMemcpyDeviceToDevice, 0);
    fill_kernel<<<(E + 255) / 256, 256>>>(ei, cursor, csr, E);

    const int gemm_grid = (N + 127) / 128;
    const int agg_grid  = (N * 32 + 255) / 256;
    const int bn_grid   = (N * 32 + 255) / 256;

    const float* hin = x;
    float* houts[LAYERS] = {hA, hB, hA};

    for (int l = 0; l < LAYERS; l++) {
        agg_csr_kernel<<<agg_grid, 256>>>(hin, rowptr, csr, agg, N);

        gemm_relu_kernel<<<gemm_grid, 256>>>(hin, agg, epsg + l,
                                             W1 + (size_t)l * HIDDEN * HIDDEN,
                                             b1 + (size_t)l * HIDDEN, tmp, N);
        gemm_relu_kernel<<<gemm_grid, 256>>>(tmp, nullptr, nullptr,
                                             W2 + (size_t)l * HIDDEN * HIDDEN,
                                             b2 + (size_t)l * HIDDEN, z2, N);

        cudaMemsetAsync(stats, 0, 2 * HIDDEN * sizeof(float), 0);
        stats_kernel<<<512, HIDDEN>>>(z2, stats, N);

        bn_pool_kernel<<<bn_grid, 256>>>(z2, stats,
                                         gamma + (size_t)l * HIDDEN,
                                         beta  + (size_t)l * HIDDEN,
                                         batch, houts[l], pool, N, l * HIDDEN);
        hin = houts[l];
    }

    head_kernel<<<NGRAPH, HIDDEN>>>(pool, cnt, l1w, l1b, l2w, l2b, out);
}

// round 13
// speedup vs baseline: 1.6129x; 1.2204x over previous
#include <cuda_runtime.h>
#include <cuda_bf16.h>
#include <cstdint>

#define HIDDEN   128
#define NGRAPH   512
#define NCLS     10
#define LAYERS   3
#define MAXN     100000
#define MAXE     1600000
#define NH       (12800000)   /* MAXN * HIDDEN */

// ---------------- scratch (device globals: no allocation allowed) ----------
__device__ float g_agg[NH];
__device__ float g_tmp[NH];
__device__ float g_zA [NH];
__device__ float g_zB [NH];
__device__ float g_pool[NGRAPH * LAYERS * HIDDEN];
__device__ float g_cnt [NGRAPH];
__device__ float g_stats[LAYERS * 2 * HIDDEN];   // per layer: colsum[128], colsumsq[128]
__device__ float g_aff  [LAYERS * 2 * HIDDEN];   // per layer: s[128], t[128]
// CSR scratch
__device__ int g_deg   [MAXN + 1];
__device__ int g_rowptr[MAXN + 1];
__device__ int g_cursor[MAXN];
__device__ int g_csr   [MAXE];
__device__ int g_bsum  [256];

// ---------------- helpers ---------------------------------------------------
__device__ __forceinline__ void red_add_v4(float* addr, float a, float b, float c, float d) {
    asm volatile("red.global.add.v4.f32 [%0], {%1, %2, %3, %4};"
                 :: "l"(addr), "f"(a), "f"(b), "f"(c), "f"(d) : "memory");
}

// ---------------- per-graph node counts -------------------------------------
__global__ void count_kernel(const int* __restrict__ batch, float* __restrict__ cnt, int N) {
    int i = blockIdx.x * blockDim.x + threadIdx.x;
    if (i < N) atomicAdd(&cnt[batch[i]], 1.0f);
}

// ---------------- CSR build --------------------------------------------------
__global__ void deg_kernel(const int* __restrict__ ei, int* __restrict__ deg, int E) {
    int e = blockIdx.x * blockDim.x + threadIdx.x;
    if (e < E) atomicAdd(&deg[ei[E + e]], 1);   // dst
}

__global__ void scan1_kernel(const int* __restrict__ in, int* __restrict__ out,
                             int* __restrict__ bsum, int M) {
    int gid = blockIdx.x * 1024 + threadIdx.x;
    int v = (gid < M) ? in[gid] : 0;
    int lane = threadIdx.x & 31, wid = threadIdx.x >> 5;
    int x = v;
#pragma unroll
    for (int o = 1; o < 32; o <<= 1) {
        int y = __shfl_up_sync(0xffffffffu, x, o);
        if (lane >= o) x += y;
    }
    __shared__ int ws[32];
    if (lane == 31) ws[wid] = x;
    __syncthreads();
    if (wid == 0) {
        int y = ws[lane];
#pragma unroll
        for (int o = 1; o < 32; o <<= 1) {
            int z = __shfl_up_sync(0xffffffffu, y, o);
            if (lane >= o) y += z;
        }
        ws[lane] = y;
    }
    __syncthreads();
    int excl = x - v + (wid > 0 ? ws[wid - 1] : 0);
    if (gid < M) out[gid] = excl;
    if (threadIdx.x == 0) bsum[blockIdx.x] = ws[31];
}

__global__ void scan2_kernel(int* __restrict__ bsum, int nb) {
    if (threadIdx.x == 0 && blockIdx.x == 0) {
        int run = 0;
        for (int i = 0; i < nb; i++) { int t = bsum[i]; bsum[i] = run; run += t; }
    }
}

__global__ void scan3_kernel(int* __restrict__ out, const int* __restrict__ bsum, int M) {
    int gid = blockIdx.x * 1024 + threadIdx.x;
    if (gid < M) out[gid] += bsum[blockIdx.x];
}

__global__ void fill_kernel(const int* __restrict__ ei, int* __restrict__ cursor,
                            int* __restrict__ csr, int E) {
    int e = blockIdx.x * blockDim.x + threadIdx.x;
    if (e < E) {
        int d = ei[E + e];
        int slot = atomicAdd(&cursor[d], 1);
        csr[slot] = ei[e];   // src
    }
}

// ---------------- CSR gather-aggregate (raw z space) -------------------------
__global__ void agg_csr_kernel(const float* __restrict__ h, const int* __restrict__ rowptr,
                               const int* __restrict__ csr, float* __restrict__ agg, int N) {
    int t = blockIdx.x * blockDim.x + threadIdx.x;
    int node = t >> 5;
    if (node >= N) return;
    int lane = t & 31;
    int s = rowptr[node], e = rowptr[node + 1];
    float4 a0 = make_float4(0.f, 0.f, 0.f, 0.f);
    float4 a1 = make_float4(0.f, 0.f, 0.f, 0.f);
    int i = s;
    for (; i + 2 <= e; i += 2) {
        int s0 = __ldg(&csr[i]);
        int s1 = __ldg(&csr[i + 1]);
        float4 v0 = ((const float4*)h)[(size_t)s0 * 32 + lane];
        float4 v1 = ((const float4*)h)[(size_t)s1 * 32 + lane];
        a0.x += v0.x; a0.y += v0.y; a0.z += v0.z; a0.w += v0.w;
        a1.x += v1.x; a1.y += v1.y; a1.z += v1.z; a1.w += v1.w;
    }
    if (i < e) {
        int s0 = __ldg(&csr[i]);
        float4 v0 = ((const float4*)h)[(size_t)s0 * 32 + lane];
        a0.x += v0.x; a0.y += v0.y; a0.z += v0.z; a0.w += v0.w;
    }
    a0.x += a1.x; a0.y += a1.y; a0.z += a1.z; a0.w += a1.w;
    ((float4*)agg)[(size_t)node * 32 + lane] = a0;
}

// ---------------- BN affine from stats ---------------------------------------
__global__ void affine_kernel(const float* __restrict__ stats,
                              const float* __restrict__ gamma, const float* __restrict__ beta,
                              float* __restrict__ aff, int N) {
    int c = threadIdx.x;
    float invN = 1.0f / (float)N;
    float mean = stats[c] * invN;
    float var  = stats[HIDDEN + c] * invN - mean * mean;
    float s = gamma[c] * rsqrtf(var + 1e-5f);
    aff[c]          = s;
    aff[HIDDEN + c] = beta[c] - mean * s;
}

// ---------------- fused SGEMM (packed f32x2) ----------------------------------
// GIN_IN:  Aeff = s⊙(alpha*A + Agg) + (alpha+deg)*t   (aff==null -> s=1,t=0)
// STATS_OUT: epilogue accumulates column sum/sumsq into stats and raw per-graph
//            pool sums into pool (layer offset loff).
template<bool GIN_IN, bool STATS_OUT>
__global__ __launch_bounds__(256, 2)
void gemm_kernel(const float* __restrict__ A, const float* __restrict__ Agg,
                 const float* __restrict__ epsp, const int* __restrict__ deg,
                 const float* __restrict__ aff,
                 const float* __restrict__ W, const float* __restrict__ bias,
                 float* __restrict__ C, int N,
                 float* __restrict__ stats, float* __restrict__ pool,
                 const int* __restrict__ batch, int loff) {
    __shared__ __align__(16) float As[32][HIDDEN + 8];
    __shared__ __align__(16) float Bs[32][HIDDEN];
    __shared__ float aff_s[HIDDEN], aff_t[HIDDEN];

    const int tid = threadIdx.x;
    const int tx = tid & 15;
    const int ty = tid >> 4;
    const int row0 = ty * 8;
    const int col0 = tx * 8;
    const int block_m = blockIdx.x * 128;

    float alpha = 1.0f;
    bool has_aff = false;
    if (GIN_IN) {
        alpha = 1.0f + __ldg(epsp);
        has_aff = (aff != nullptr);
        if (has_aff && tid < HIDDEN) {
            aff_s[tid] = aff[tid];
            aff_t[tid] = aff[HIDDEN + tid];
        }
        if (has_aff) __syncthreads();
    }

    unsigned long long acc[4][8];
#pragma unroll
    for (int i = 0; i < 4; i++)
#pragma unroll
        for (int j = 0; j < 8; j++) acc[i][j] = 0ull;

    for (int kk = 0; kk < HIDDEN; kk += 32) {
#pragma unroll
        for (int it = 0; it < 4; it++) {
            int flat = tid + it * 256;
            int m    = flat >> 3;
            int k4   = (flat & 7) * 4;
            int gm   = block_m + m;
            float4 v = make_float4(0.f, 0.f, 0.f, 0.f);
            if (gm < N) {
                v = *(const float4*)(A + (size_t)gm * HIDDEN + kk + k4);
                if (GIN_IN) {
                    float4 u = *(const float4*)(Agg + (size_t)gm * HIDDEN + kk + k4);
                    v.x = fmaf(alpha, v.x, u.x);
                    v.y = fmaf(alpha, v.y, u.y);
                    v.z = fmaf(alpha, v.z, u.z);
                    v.w = fmaf(alpha, v.w, u.w);
                    if (has_aff) {
                        float coef = alpha + (float)__ldg(&deg[gm]);
                        int c = kk + k4;
                        v.x = fmaf(aff_s[c + 0], v.x, coef * aff_t[c + 0]);
                        v.y = fmaf(aff_s[c + 1], v.y, coef * aff_t[c + 1]);
                        v.z = fmaf(aff_s[c + 2], v.z, coef * aff_t[c + 2]);
                        v.w = fmaf(aff_s[c + 3], v.w, coef * aff_t[c + 3]);
                    }
                }
            }
            As[k4 + 0][m] = v.x;
            As[k4 + 1][m] = v.y;
            As[k4 + 2][m] = v.z;
            As[k4 + 3][m] = v.w;
        }
#pragma unroll
        for (int it = 0; it < 4; it++) {
            int flat = tid + it * 256;
            int k    = flat >> 5;
            int n4   = (flat & 31) * 4;
            *(float4*)&Bs[k][n4] = *(const float4*)(W + (size_t)(kk + k) * HIDDEN + n4);
        }
        __syncthreads();

#pragma unroll 8
        for (int k = 0; k < 32; k++) {
            ulonglong2 A0 = *(const ulonglong2*)&As[k][row0];
            ulonglong2 A1 = *(const ulonglong2*)&As[k][row0 + 4];
            unsigned long long ap[4] = {A0.x, A0.y, A1.x, A1.y};
            float4 b0 = *(const float4*)&Bs[k][col0];
            float4 b1 = *(const float4*)&Bs[k][col0 + 4];
            float bb[8] = {b0.x, b0.y, b0.z, b0.w, b1.x, b1.y, b1.z, b1.w};
            unsigned long long bd[8];
#pragma unroll
            for (int j = 0; j < 8; j++)
                asm("mov.b64 %0, {%1, %1};" : "=l"(bd[j]) : "f"(bb[j]));
#pragma unroll
            for (int i2 = 0; i2 < 4; i2++)
#pragma unroll
                for (int j = 0; j < 8; j++)
                    asm("fma.rn.f32x2 %0, %1, %2, %0;"
                        : "+l"(acc[i2][j]) : "l"(ap[i2]), "l"(bd[j]));
        }
        __syncthreads();
    }

    float o[8][8];
#pragma unroll
    for (int i2 = 0; i2 < 4; i2++)
#pragma unroll
        for (int j = 0; j < 8; j++)
            asm("mov.b64 {%0, %1}, %2;"
                : "=f"(o[2 * i2][j]), "=f"(o[2 * i2 + 1][j]) : "l"(acc[i2][j]));

    float bv[8];
#pragma unroll
    for (int j = 0; j < 8; j++) bv[j] = bias[col0 + j];

#pragma unroll
    for (int i = 0; i < 8; i++) {
#pragma unroll
        for (int j = 0; j < 8; j++) o[i][j] = fmaxf(o[i][j] + bv[j], 0.f);
        int gm = block_m + row0 + i;
        if (gm < N) {
            *(float4*)(C + (size_t)gm * HIDDEN + col0)     = *(float4*)&o[i][0];
            *(float4*)(C + (size_t)gm * HIDDEN + col0 + 4) = *(float4*)&o[i][4];
            if (STATS_OUT) {
                int b = __ldg(&batch[gm]);
                float* p = pool + (size_t)b * (LAYERS * HIDDEN) + loff + col0;
                red_add_v4(p,     o[i][0], o[i][1], o[i][2], o[i][3]);
                red_add_v4(p + 4, o[i][4], o[i][5], o[i][6], o[i][7]);
            }
        }
    }

    if (STATS_OUT) {
        // per-CTA column sum/sumsq reduction, reusing As smem (loop ended with sync)
        float psum[8], psq[8];
#pragma unroll
        for (int j = 0; j < 8; j++) { psum[j] = 0.f; psq[j] = 0.f; }
#pragma unroll
        for (int i = 0; i < 8; i++) {
            int gm = block_m + row0 + i;
            if (gm < N) {
#pragma unroll
                for (int j = 0; j < 8; j++) {
                    psum[j] += o[i][j];
                    psq[j]  += o[i][j] * o[i][j];
                }
            }
        }
        float* red = &As[0][0];   // 4352 floats available; use 4096
#pragma unroll
        for (int j = 0; j < 8; j += 4) {
            *(float4*)&red[ty * 128 + col0 + j]        = *(float4*)&psum[j];
            *(float4*)&red[2048 + ty * 128 + col0 + j] = *(float4*)&psq[j];
        }
        __syncthreads();
        if (tid < HIDDEN) {
            float s = 0.f, q = 0.f;
#pragma unroll
            for (int t = 0; t < 16; t++) {
                s += red[t * 128 + tid];
                q += red[2048 + t * 128 + tid];
            }
            atomicAdd(&stats[tid], s);
            atomicAdd(&stats[HIDDEN + tid], q);
        }
    }
}

// ---------------- readout head (applies BN affine to raw pools) --------------
__global__ void head_kernel(const float* __restrict__ pool, const float* __restrict__ cnt,
                            const float* __restrict__ aff,
                            const float* __restrict__ l1w, const float* __restrict__ l1b,
                            const float* __restrict__ l2w, const float* __restrict__ l2b,
                            float* __restrict__ out) {
    __shared__ float grow[LAYERS * HIDDEN];
    __shared__ float o1[HIDDEN];
    int g = blockIdx.x, t = threadIdx.x;
    float c0 = cnt[g];
    float inv = 1.0f / fmaxf(c0, 1.0f);
    for (int j = t; j < LAYERS * HIDDEN; j += HIDDEN) {
        int l = j >> 7, c = j & 127;
        float raw = pool[(size_t)g * (LAYERS * HIDDEN) + j];
        float s = aff[l * 2 * HIDDEN + c];
        float tt = aff[l * 2 * HIDDEN + HIDDEN + c];
        grow[j] = (s * raw + c0 * tt) * inv;
    }
    __syncthreads();

    float acc = l1b[t];
    for (int j = 0; j < LAYERS * HIDDEN; j++)
        acc = fmaf(grow[j], l1w[(size_t)j * HIDDEN + t], acc);
    o1[t] = fmaxf(acc, 0.f);
    __syncthreads();

    if (t < NCLS) {
        float a = l2b[t];
        for (int c2 = 0; c2 < HIDDEN; c2++)
            a = fmaf(o1[c2], l2w[(size_t)c2 * NCLS + t], a);
        out[(size_t)g * NCLS + t] = a;
    }
}

// ---------------- launcher ----------------------------------------------------
extern "C" void kernel_launch(void* const* d_in, const int* in_sizes, int n_in,
                              void* d_out, int out_size) {
    const float* x     = (const float*)d_in[0];
    const int*   ei    = (const int*)  d_in[1];
    const int*   batch = (const int*)  d_in[2];
    const float* W1    = (const float*)d_in[3];
    const float* b1    = (const float*)d_in[4];
    const float* W2    = (const float*)d_in[5];
    const float* b2    = (const float*)d_in[6];
    const float* gamma = (const float*)d_in[7];
    const float* beta  = (const float*)d_in[8];
    const float* epsg  = (const float*)d_in[9];
    const float* l1w   = (const float*)d_in[10];
    const float* l1b   = (const float*)d_in[11];
    const float* l2w   = (const float*)d_in[12];
    const float* l2b   = (const float*)d_in[13];
    float* out = (float*)d_out;

    const int N = in_sizes[0] / HIDDEN;
    const int E = in_sizes[1] / 2;
    const int M = N + 1;

    float *agg, *tmp, *zA, *zB, *pool, *cnt, *stats, *aff;
    int *deg, *rowptr, *cursor, *csr, *bsum;
    cudaGetSymbolAddress((void**)&agg,    g_agg);
    cudaGetSymbolAddress((void**)&tmp,    g_tmp);
    cudaGetSymbolAddress((void**)&zA,     g_zA);
    cudaGetSymbolAddress((void**)&zB,     g_zB);
    cudaGetSymbolAddress((void**)&pool,   g_pool);
    cudaGetSymbolAddress((void**)&cnt,    g_cnt);
    cudaGetSymbolAddress((void**)&stats,  g_stats);
    cudaGetSymbolAddress((void**)&aff,    g_aff);
    cudaGetSymbolAddress((void**)&deg,    g_deg);
    cudaGetSymbolAddress((void**)&rowptr, g_rowptr);
    cudaGetSymbolAddress((void**)&cursor, g_cursor);
    cudaGetSymbolAddress((void**)&csr,    g_csr);
    cudaGetSymbolAddress((void**)&bsum,   g_bsum);

    cudaMemsetAsync(pool,  0, (size_t)NGRAPH * LAYERS * HIDDEN * sizeof(float), 0);
    cudaMemsetAsync(cnt,   0, (size_t)NGRAPH * sizeof(float), 0);
    cudaMemsetAsync(stats, 0, (size_t)LAYERS * 2 * HIDDEN * sizeof(float), 0);
    count_kernel<<<(N + 255) / 256, 256>>>(batch, cnt, N);

    // ---- CSR build (once) ----
    const int nb = (M + 1023) / 1024;
    cudaMemsetAsync(deg, 0, (size_t)M * sizeof(int), 0);
    deg_kernel<<<(E + 255) / 256, 256>>>(ei, deg, E);
    scan1_kernel<<<nb, 1024>>>(deg, rowptr, bsum, M);
    scan2_kernel<<<1, 32>>>(bsum, nb);
    scan3_kernel<<<nb, 1024>>>(rowptr, bsum, M);
    cudaMemcpyAsync(cursor, rowptr, (size_t)N * sizeof(int), cudaMemcpyDeviceToDevice, 0);
    fill_kernel<<<(E + 255) / 256, 256>>>(ei, cursor, csr, E);

    const int gemm_grid = (N + 127) / 128;
    const int agg_grid  = (N * 32 + 255) / 256;

    const float* zin = x;                       // raw (pre-BN) features of previous layer
    float* zouts[LAYERS] = {zA, zB, zA};

    for (int l = 0; l < LAYERS; l++) {
        agg_csr_kernel<<<agg_grid, 256>>>(zin, rowptr, csr, agg, N);

        const float* aff_prev = (l == 0) ? nullptr : (aff + (size_t)(l - 1) * 2 * HIDDEN);
        gemm_kernel<true, false><<<gemm_grid, 256>>>(
            zin, agg, epsg + l, deg, aff_prev,
            W1 + (size_t)l * HIDDEN * HIDDEN, b1 + (size_t)l * HIDDEN,
            tmp, N, nullptr, nullptr, nullptr, 0);

        gemm_kernel<false, true><<<gemm_grid, 256>>>(
            tmp, nullptr, nullptr, nullptr, nullptr,
            W2 + (size_t)l * HIDDEN * HIDDEN, b2 + (size_t)l * HIDDEN,
            zouts[l], N, stats + (size_t)l * 2 * HIDDEN, pool, batch, l * HIDDEN);

        affine_kernel<<<1, HIDDEN>>>(stats + (size_t)l * 2 * HIDDEN,
                                     gamma + (size_t)l * HIDDEN,
                                     beta  + (size_t)l * HIDDEN,
                                     aff + (size_t)l * 2 * HIDDEN, N);
        zin = zouts[l];
    }

    head_kernel<<<NGRAPH, HIDDEN>>>(pool, cnt, aff, l1w, l1b, l2w, l2b, out);
}